// round 5
// baseline (speedup 1.0000x reference)
#include <cuda_runtime.h>
#include <math.h>

// Problem constants
#define BB 2
#define LL 2048
#define DD 2048
#define HH 16
#define HDIM 128

// Packed fp32x2 math (Blackwell FFMA2 path — only reachable via inline PTX)
#define FMA2(d, a, b, c) \
    asm("fma.rn.f32x2 %0, %1, %2, %3;" : "=l"(d) : "l"(a), "l"(b), "l"(c))
#define MUL2(d, a, b) \
    asm("mul.rn.f32x2 %0, %1, %2;" : "=l"(d) : "l"(a), "l"(b))
#define PACK_DUP(d, x) \
    asm("mov.b64 %0, {%1, %1};" : "=l"(d) : "r"(__float_as_uint(x)))
#define PACK_PAIR(d, x, y) \
    asm("mov.b64 %0, {%1, %2};" : "=l"(d) : "r"(__float_as_uint(x)), "r"(__float_as_uint(y)))
#define UNPACK2(lo, hi, s) do { \
    unsigned int _ulo, _uhi; \
    asm("mov.b64 {%0, %1}, %2;" : "=r"(_ulo), "=r"(_uhi) : "l"(s)); \
    lo = __uint_as_float(_ulo); hi = __uint_as_float(_uhi); \
} while (0)

typedef unsigned long long u64;

// Scratch (allocation-free contract: __device__ globals)
__device__ float g_qkv[(size_t)BB * LL * 3 * DD];   // [b,l, q|k|v on last axis]
__device__ float g_att[(size_t)BB * LL * DD];       // attention output, [b,l,h*HD]

// ---------------------------------------------------------------------------
// GEMM: C[M,N] = A[M,K] @ B[N,K]^T   (row-major, K contiguous -> NT GEMM)
// 128x128 block tile, 8x8 per-thread microtile (as 8x4 f32x2 pairs),
// K-step 8, 256 threads, double-buffered smem.
// Optional fused RoPE epilogue for output cols < ropeCols.
// ---------------------------------------------------------------------------
__global__ __launch_bounds__(256, 2)
void gemm_nt(const float* __restrict__ A, const float* __restrict__ Bm,
             float* __restrict__ C, int M, int N, int K,
             const float* __restrict__ cosT, const float* __restrict__ sinT,
             int ropeCols) {
    __shared__ __align__(16) float As[2][8][128];
    __shared__ __align__(16) float Bs[2][8][128];

    const int tid = threadIdx.x;
    const int tx = tid & 15;          // N microtile
    const int ty = tid >> 4;          // M microtile
    const int row0 = blockIdx.y * 128;
    const int col0 = blockIdx.x * 128;

    const int ar = tid >> 1;          // 0..127
    const int ac = (tid & 1) * 4;     // 0 or 4

    u64 c2[8][4];
#pragma unroll
    for (int i = 0; i < 8; i++)
#pragma unroll
        for (int j = 0; j < 4; j++) c2[i][j] = 0ULL;

    const float* Ap = A + (size_t)(row0 + ar) * K + ac;
    const float* Bp = Bm + (size_t)(col0 + ar) * K + ac;

    // Prologue: slab 0 -> buffer 0
    {
        float4 av = *(const float4*)(Ap);
        float4 bv = *(const float4*)(Bp);
        As[0][ac + 0][ar] = av.x; As[0][ac + 1][ar] = av.y;
        As[0][ac + 2][ar] = av.z; As[0][ac + 3][ar] = av.w;
        Bs[0][ac + 0][ar] = bv.x; Bs[0][ac + 1][ar] = bv.y;
        Bs[0][ac + 2][ar] = bv.z; Bs[0][ac + 3][ar] = bv.w;
    }
    __syncthreads();

    int buf = 0;
    for (int k0 = 8; k0 < K; k0 += 8) {
        float4 av = *(const float4*)(Ap + k0);   // prefetch next slab
        float4 bv = *(const float4*)(Bp + k0);

#pragma unroll
        for (int kk = 0; kk < 8; kk++) {
            float a[8];
            *(float4*)&a[0] = *(const float4*)&As[buf][kk][ty * 8];
            *(float4*)&a[4] = *(const float4*)&As[buf][kk][ty * 8 + 4];
            const u64* bp2 = (const u64*)&Bs[buf][kk][tx * 8];
            u64 b2[4];
            b2[0] = bp2[0]; b2[1] = bp2[1]; b2[2] = bp2[2]; b2[3] = bp2[3];
#pragma unroll
            for (int i = 0; i < 8; i++) {
                u64 a2; PACK_DUP(a2, a[i]);
#pragma unroll
                for (int j = 0; j < 4; j++)
                    FMA2(c2[i][j], a2, b2[j], c2[i][j]);
            }
        }

        const int nb = buf ^ 1;
        As[nb][ac + 0][ar] = av.x; As[nb][ac + 1][ar] = av.y;
        As[nb][ac + 2][ar] = av.z; As[nb][ac + 3][ar] = av.w;
        Bs[nb][ac + 0][ar] = bv.x; Bs[nb][ac + 1][ar] = bv.y;
        Bs[nb][ac + 2][ar] = bv.z; Bs[nb][ac + 3][ar] = bv.w;
        __syncthreads();
        buf = nb;
    }

    // Epilogue slab
#pragma unroll
    for (int kk = 0; kk < 8; kk++) {
        float a[8];
        *(float4*)&a[0] = *(const float4*)&As[buf][kk][ty * 8];
        *(float4*)&a[4] = *(const float4*)&As[buf][kk][ty * 8 + 4];
        const u64* bp2 = (const u64*)&Bs[buf][kk][tx * 8];
        u64 b2[4];
        b2[0] = bp2[0]; b2[1] = bp2[1]; b2[2] = bp2[2]; b2[3] = bp2[3];
#pragma unroll
        for (int i = 0; i < 8; i++) {
            u64 a2; PACK_DUP(a2, a[i]);
#pragma unroll
            for (int j = 0; j < 4; j++)
                FMA2(c2[i][j], a2, b2[j], c2[i][j]);
        }
    }

    // Epilogue: optional fused RoPE (uniform per block).
    const bool doRope = (col0 < ropeCols);
    const int colBase = col0 + tx * 8;
    const int dBase = colBase & (DD - 1);    // feature index within D

#pragma unroll
    for (int i = 0; i < 8; i++) {
        float v[8];
#pragma unroll
        for (int j = 0; j < 4; j++) UNPACK2(v[2 * j], v[2 * j + 1], c2[i][j]);

        const int row = row0 + ty * 8 + i;
        if (doRope) {
            const int l = row & (LL - 1);
            const float* cp = cosT + (size_t)l * DD + dBase;
            const float* sp = sinT + (size_t)l * DD + dBase;
#pragma unroll
            for (int j = 0; j < 4; j++) {
                float c0 = cp[2 * j];        // cos repeated over the pair
                float s0 = sp[2 * j];
                float x0 = v[2 * j], x1 = v[2 * j + 1];
                v[2 * j]     = x0 * c0 - x1 * s0;
                v[2 * j + 1] = x1 * c0 + x0 * s0;
            }
        }

        float* Cp = C + (size_t)row * N + colBase;
        *(float4*)&Cp[0] = make_float4(v[0], v[1], v[2], v[3]);
        *(float4*)&Cp[4] = make_float4(v[4], v[5], v[6], v[7]);
    }
}

// ---------------------------------------------------------------------------
// Flash attention, fp32 (f32x2 math), causal. One block = (b,h,q-tile of 64).
// 256 threads: t = rb*16 + cb; rb owns rows rb*4..rb*4+3 in both phases.
//   S-phase:  S[rb*4+i][cb + 16*j]
//   PV-phase: O[rb*4+i][cb*2 + j*32 + {0,1}]  (conflict-free LDS.64 on Vs)
// ---------------------------------------------------------------------------
#define QK_STRIDE 130
#define SMEM_ATT_FLOATS (64 * QK_STRIDE * 2 + 64 * 128 + 64 * 64)
#define SMEM_ATT_BYTES  (SMEM_ATT_FLOATS * 4)

__global__ __launch_bounds__(256, 1)
void attn_kernel(const float* __restrict__ qkv, float* __restrict__ out) {
    extern __shared__ float sm[];
    float* Qs = sm;                         // 64 x 130
    float* Ks = Qs + 64 * QK_STRIDE;        // 64 x 130
    float* Vs = Ks + 64 * QK_STRIDE;        // 64 x 128
    float* Ps = Vs + 64 * 128;              // 64 x 64

    const int t  = threadIdx.x;
    const int rb = t >> 4;
    const int cb = t & 15;
    const int bh = blockIdx.y;
    const int b  = bh >> 4;
    const int h  = bh & 15;
    const int nqt = LL / 64;
    const int qt = nqt - 1 - blockIdx.x;    // reversed for causal load balance
    const int q0 = qt * 64;

    const float scale = 0.08838834764831845f;  // 1/sqrt(128)
    const float* base = qkv + (size_t)b * LL * 3 * DD + h * HDIM;

    for (int idx = t; idx < 64 * HDIM; idx += 256) {
        int r = idx >> 7, d = idx & 127;
        Qs[r * QK_STRIDE + d] = base[(size_t)(q0 + r) * (3 * DD) + d] * scale;
    }

    float m[4], lsum[4];
    u64 o2[4][4];
#pragma unroll
    for (int i = 0; i < 4; i++) {
        m[i] = -1e30f; lsum[i] = 0.f;
#pragma unroll
        for (int j = 0; j < 4; j++) o2[i][j] = 0ULL;
    }
    __syncthreads();

    for (int kb = 0; kb <= qt; kb++) {
        const int k0 = kb * 64;
        // K tile: scalar loads (stride-130 store side must stay scalar)
        for (int idx = t; idx < 64 * HDIM; idx += 256) {
            int r = idx >> 7, d = idx & 127;
            Ks[r * QK_STRIDE + d] = base[(size_t)(k0 + r) * (3 * DD) + DD + d];
        }
        // V tile: float4 both sides (stride-128 layout is 16B-clean)
        for (int idx = t; idx < (64 * HDIM) / 4; idx += 256) {
            int r = idx >> 5, d4 = (idx & 31) << 2;
            float4 vv = *(const float4*)&base[(size_t)(k0 + r) * (3 * DD) + 2 * DD + d4];
            *(float4*)&Vs[r * 128 + d4] = vv;
        }
        __syncthreads();

        // S = Q K^T : acc pairs over j ({0,1},{2,3}) as f32x2
        u64 acc2[4][2];
#pragma unroll
        for (int i = 0; i < 4; i++) { acc2[i][0] = 0ULL; acc2[i][1] = 0ULL; }

#pragma unroll 4
        for (int d = 0; d < HDIM; d++) {
            u64 kv2[2];
            {
                float k0v = Ks[(cb +  0) * QK_STRIDE + d];
                float k1v = Ks[(cb + 16) * QK_STRIDE + d];
                float k2v = Ks[(cb + 32) * QK_STRIDE + d];
                float k3v = Ks[(cb + 48) * QK_STRIDE + d];
                PACK_PAIR(kv2[0], k0v, k1v);
                PACK_PAIR(kv2[1], k2v, k3v);
            }
#pragma unroll
            for (int i = 0; i < 4; i++) {
                u64 q2; PACK_DUP(q2, Qs[(rb * 4 + i) * QK_STRIDE + d]);
                FMA2(acc2[i][0], q2, kv2[0], acc2[i][0]);
                FMA2(acc2[i][1], q2, kv2[1], acc2[i][1]);
            }
        }

        // Unpack, causal mask + online softmax (row stats in registers)
        float alpha[4];
#pragma unroll
        for (int i = 0; i < 4; i++) {
            float acc[4];
            UNPACK2(acc[0], acc[1], acc2[i][0]);
            UNPACK2(acc[2], acc[3], acc2[i][1]);
            const int qrow = q0 + rb * 4 + i;
            float mx = -1e30f;
#pragma unroll
            for (int j = 0; j < 4; j++) {
                int kcol = k0 + cb + 16 * j;
                if (kcol > qrow) acc[j] = -1e30f;
                mx = fmaxf(mx, acc[j]);
            }
#pragma unroll
            for (int off = 8; off >= 1; off >>= 1)
                mx = fmaxf(mx, __shfl_xor_sync(0xffffffffu, mx, off));
            float mnew = fmaxf(m[i], mx);
            float p[4], s = 0.f;
#pragma unroll
            for (int j = 0; j < 4; j++) { p[j] = __expf(acc[j] - mnew); s += p[j]; }
#pragma unroll
            for (int off = 8; off >= 1; off >>= 1)
                s += __shfl_xor_sync(0xffffffffu, s, off);
            float al = __expf(m[i] - mnew);
            m[i] = mnew;
            lsum[i] = lsum[i] * al + s;
            alpha[i] = al;
#pragma unroll
            for (int j = 0; j < 4; j++)
                Ps[(rb * 4 + i) * 64 + cb + 16 * j] = p[j];
        }
        __syncthreads();

        // O = O*alpha + P V ; thread cb owns col pairs {cb*2 + j*32}
#pragma unroll
        for (int i = 0; i < 4; i++) {
            u64 al2; PACK_DUP(al2, alpha[i]);
#pragma unroll
            for (int j = 0; j < 4; j++) MUL2(o2[i][j], o2[i][j], al2);
        }

#pragma unroll 2
        for (int k = 0; k < 64; k++) {
            u64 v2[4];
#pragma unroll
            for (int j = 0; j < 4; j++)
                v2[j] = *(const u64*)&Vs[k * 128 + cb * 2 + j * 32];
#pragma unroll
            for (int i = 0; i < 4; i++) {
                u64 p2; PACK_DUP(p2, Ps[(rb * 4 + i) * 64 + k]);
                FMA2(o2[i][0], p2, v2[0], o2[i][0]);
                FMA2(o2[i][1], p2, v2[1], o2[i][1]);
                FMA2(o2[i][2], p2, v2[2], o2[i][2]);
                FMA2(o2[i][3], p2, v2[3], o2[i][3]);
            }
        }
        __syncthreads();
    }

    // Epilogue: normalize + write; thread cb writes float2 at cols cb*2 + j*32
#pragma unroll
    for (int i = 0; i < 4; i++) {
        float inv = 1.f / lsum[i];
        int row = q0 + rb * 4 + i;
        float* op = out + ((size_t)(b * LL + row)) * DD + h * HDIM;
#pragma unroll
        for (int j = 0; j < 4; j++) {
            float x0, x1;
            UNPACK2(x0, x1, o2[i][j]);
            *(float2*)&op[cb * 2 + j * 32] = make_float2(x0 * inv, x1 * inv);
        }
    }
}

// ---------------------------------------------------------------------------
// Launch
// ---------------------------------------------------------------------------
extern "C" void kernel_launch(void* const* d_in, const int* in_sizes, int n_in,
                              void* d_out, int out_size) {
    const float* x    = (const float*)d_in[0];
    const float* cosT = (const float*)d_in[1];
    const float* sinT = (const float*)d_in[2];
    const float* Wqkv = (const float*)d_in[3];
    const float* Wo   = (const float*)d_in[4];
    float* out = (float*)d_out;

    float *qkv, *att;
    cudaGetSymbolAddress((void**)&qkv, g_qkv);
    cudaGetSymbolAddress((void**)&att, g_att);

    // 1) QKV projection with fused RoPE on the q,k regions (cols < 2*DD)
    gemm_nt<<<dim3(6144 / 128, 4096 / 128), 256>>>(x, Wqkv, qkv,
                                                   BB * LL, 3 * DD, DD,
                                                   cosT, sinT, 2 * DD);

    // 2) Causal flash attention
    cudaFuncSetAttribute(attn_kernel, cudaFuncAttributeMaxDynamicSharedMemorySize,
                         SMEM_ATT_BYTES);
    attn_kernel<<<dim3(LL / 64, BB * HH), 256, SMEM_ATT_BYTES>>>(qkv, att);

    // 3) Output projection: [4096,2048] @ [2048,2048]^T -> d_out
    gemm_nt<<<dim3(2048 / 128, 4096 / 128), 256>>>(att, Wo, out,
                                                   BB * LL, DD, DD,
                                                   (const float*)0, (const float*)0, 0);
}

// round 10
// speedup vs baseline: 1.0427x; 1.0427x over previous
#include <cuda_runtime.h>
#include <math.h>

// Problem constants
#define BB 2
#define LL 2048
#define DD 2048
#define HH 16
#define HDIM 128

// Packed fp32x2 math (Blackwell FFMA2 path — only reachable via inline PTX)
#define FMA2(d, a, b, c) \
    asm("fma.rn.f32x2 %0, %1, %2, %3;" : "=l"(d) : "l"(a), "l"(b), "l"(c))
#define MUL2(d, a, b) \
    asm("mul.rn.f32x2 %0, %1, %2;" : "=l"(d) : "l"(a), "l"(b))
#define PACK_DUP(d, x) \
    asm("mov.b64 %0, {%1, %1};" : "=l"(d) : "r"(__float_as_uint(x)))
#define UNPACK2(lo, hi, s) do { \
    unsigned int _ulo, _uhi; \
    asm("mov.b64 {%0, %1}, %2;" : "=r"(_ulo), "=r"(_uhi) : "l"(s)); \
    lo = __uint_as_float(_ulo); hi = __uint_as_float(_uhi); \
} while (0)

typedef unsigned long long u64;

// Scratch (allocation-free contract: __device__ globals)
__device__ float g_qkv[(size_t)BB * LL * 3 * DD];   // [b,l, q|k|v on last axis]
__device__ float g_att[(size_t)BB * LL * DD];       // attention output, [b,l,h*HD]

// ---------------------------------------------------------------------------
// GEMM: C[M,N] = A[M,K] @ B[N,K]^T   (row-major, K contiguous -> NT GEMM)
// 128x128 block tile, 8 rows x (4 strided col-pairs) per thread, K-step 8,
// 256 threads, double-buffered smem.
// Thread tx owns output col pairs {tx*2 + j*32, +1} -> conflict-free LDS.64
// on the B fragment (banks 2tx, 2tx+1 cover all 32 banks exactly once).
// Optional fused RoPE epilogue for output cols < ropeCols (pairs adjacent).
// ---------------------------------------------------------------------------
__global__ __launch_bounds__(256, 2)
void gemm_nt(const float* __restrict__ A, const float* __restrict__ Bm,
             float* __restrict__ C, int M, int N, int K,
             const float* __restrict__ cosT, const float* __restrict__ sinT,
             int ropeCols) {
    __shared__ __align__(16) float As[2][8][128];
    __shared__ __align__(16) float Bs[2][8][128];

    const int tid = threadIdx.x;
    const int tx = tid & 15;          // N microtile (strided pairs)
    const int ty = tid >> 4;          // M microtile
    const int row0 = blockIdx.y * 128;
    const int col0 = blockIdx.x * 128;

    const int ar = tid >> 1;          // 0..127
    const int ac = (tid & 1) * 4;     // 0 or 4

    u64 c2[8][4];
#pragma unroll
    for (int i = 0; i < 8; i++)
#pragma unroll
        for (int j = 0; j < 4; j++) c2[i][j] = 0ULL;

    const float* Ap = A + (size_t)(row0 + ar) * K + ac;
    const float* Bp = Bm + (size_t)(col0 + ar) * K + ac;

    // Prologue: slab 0 -> buffer 0
    {
        float4 av = *(const float4*)(Ap);
        float4 bv = *(const float4*)(Bp);
        As[0][ac + 0][ar] = av.x; As[0][ac + 1][ar] = av.y;
        As[0][ac + 2][ar] = av.z; As[0][ac + 3][ar] = av.w;
        Bs[0][ac + 0][ar] = bv.x; Bs[0][ac + 1][ar] = bv.y;
        Bs[0][ac + 2][ar] = bv.z; Bs[0][ac + 3][ar] = bv.w;
    }
    __syncthreads();

    int buf = 0;
    for (int k0 = 8; k0 < K; k0 += 8) {
        float4 av = *(const float4*)(Ap + k0);   // prefetch next slab
        float4 bv = *(const float4*)(Bp + k0);

#pragma unroll
        for (int kk = 0; kk < 8; kk++) {
            float a[8];
            *(float4*)&a[0] = *(const float4*)&As[buf][kk][ty * 8];
            *(float4*)&a[4] = *(const float4*)&As[buf][kk][ty * 8 + 4];
            u64 b2[4];
#pragma unroll
            for (int j = 0; j < 4; j++)
                b2[j] = *(const u64*)&Bs[buf][kk][tx * 2 + j * 32];
#pragma unroll
            for (int i = 0; i < 8; i++) {
                u64 a2; PACK_DUP(a2, a[i]);
#pragma unroll
                for (int j = 0; j < 4; j++)
                    FMA2(c2[i][j], a2, b2[j], c2[i][j]);
            }
        }

        const int nb = buf ^ 1;
        As[nb][ac + 0][ar] = av.x; As[nb][ac + 1][ar] = av.y;
        As[nb][ac + 2][ar] = av.z; As[nb][ac + 3][ar] = av.w;
        Bs[nb][ac + 0][ar] = bv.x; Bs[nb][ac + 1][ar] = bv.y;
        Bs[nb][ac + 2][ar] = bv.z; Bs[nb][ac + 3][ar] = bv.w;
        __syncthreads();
        buf = nb;
    }

    // Epilogue slab
#pragma unroll
    for (int kk = 0; kk < 8; kk++) {
        float a[8];
        *(float4*)&a[0] = *(const float4*)&As[buf][kk][ty * 8];
        *(float4*)&a[4] = *(const float4*)&As[buf][kk][ty * 8 + 4];
        u64 b2[4];
#pragma unroll
        for (int j = 0; j < 4; j++)
            b2[j] = *(const u64*)&Bs[buf][kk][tx * 2 + j * 32];
#pragma unroll
        for (int i = 0; i < 8; i++) {
            u64 a2; PACK_DUP(a2, a[i]);
#pragma unroll
            for (int j = 0; j < 4; j++)
                FMA2(c2[i][j], a2, b2[j], c2[i][j]);
        }
    }

    // Epilogue: optional fused RoPE (uniform per block); pairs are adjacent
    // (col = tx*2 + j*32 is even), so rotation stays thread-local.
    const bool doRope = (col0 < ropeCols);
    const int colBase = col0 + tx * 2;

#pragma unroll
    for (int i = 0; i < 8; i++) {
        const int row = row0 + ty * 8 + i;
        const int l = row & (LL - 1);
        float* Cp = C + (size_t)row * N;
#pragma unroll
        for (int j = 0; j < 4; j++) {
            float x0, x1;
            UNPACK2(x0, x1, c2[i][j]);
            const int col = colBase + j * 32;
            if (doRope) {
                const int dj = col & (DD - 1);
                float c0 = cosT[(size_t)l * DD + dj];
                float s0 = sinT[(size_t)l * DD + dj];
                float t0 = x0 * c0 - x1 * s0;
                x1 = x1 * c0 + x0 * s0;
                x0 = t0;
            }
            *(float2*)&Cp[col] = make_float2(x0, x1);
        }
    }
}

// ---------------------------------------------------------------------------
// Flash attention, fp32 (f32x2 math), causal. One block = (b,h,q-tile of 64).
// 256 threads: t = rb*16 + cb; rb owns rows rb*4..rb*4+3 in both phases.
//   S-phase:  d-paired f32x2 accumulation (LDS.64 on contiguous d-pairs of
//             Qs and Ks; horizontal add at the end). Columns cb + 16*j.
//   PV-phase: O[rb*4+i][cb*2 + j*32 + {0,1}]  (conflict-free LDS.64 on Vs)
// ---------------------------------------------------------------------------
#define QK_STRIDE 130
#define SMEM_ATT_FLOATS (64 * QK_STRIDE * 2 + 64 * 128 + 64 * 64)
#define SMEM_ATT_BYTES  (SMEM_ATT_FLOATS * 4)

__global__ __launch_bounds__(256, 1)
void attn_kernel(const float* __restrict__ qkv, float* __restrict__ out) {
    extern __shared__ float sm[];
    float* Qs = sm;                         // 64 x 130
    float* Ks = Qs + 64 * QK_STRIDE;        // 64 x 130
    float* Vs = Ks + 64 * QK_STRIDE;        // 64 x 128
    float* Ps = Vs + 64 * 128;              // 64 x 64

    const int t  = threadIdx.x;
    const int rb = t >> 4;
    const int cb = t & 15;
    const int bh = blockIdx.y;
    const int b  = bh >> 4;
    const int h  = bh & 15;
    const int nqt = LL / 64;
    const int qt = nqt - 1 - blockIdx.x;    // reversed for causal load balance
    const int q0 = qt * 64;

    const float scale = 0.08838834764831845f;  // 1/sqrt(128)
    const float* base = qkv + (size_t)b * LL * 3 * DD + h * HDIM;

    for (int idx = t; idx < 64 * HDIM; idx += 256) {
        int r = idx >> 7, d = idx & 127;
        Qs[r * QK_STRIDE + d] = base[(size_t)(q0 + r) * (3 * DD) + d] * scale;
    }

    float m[4], lsum[4];
    u64 o2[4][4];
#pragma unroll
    for (int i = 0; i < 4; i++) {
        m[i] = -1e30f; lsum[i] = 0.f;
#pragma unroll
        for (int j = 0; j < 4; j++) o2[i][j] = 0ULL;
    }
    __syncthreads();

    for (int kb = 0; kb <= qt; kb++) {
        const int k0 = kb * 64;
        // K tile: scalar loads (stride-130 store side must stay scalar)
        for (int idx = t; idx < 64 * HDIM; idx += 256) {
            int r = idx >> 7, d = idx & 127;
            Ks[r * QK_STRIDE + d] = base[(size_t)(k0 + r) * (3 * DD) + DD + d];
        }
        // V tile: float4 both sides (stride-128 layout is 16B-clean)
        for (int idx = t; idx < (64 * HDIM) / 4; idx += 256) {
            int r = idx >> 5, d4 = (idx & 31) << 2;
            float4 vv = *(const float4*)&base[(size_t)(k0 + r) * (3 * DD) + 2 * DD + d4];
            *(float4*)&Vs[r * 128 + d4] = vv;
        }
        __syncthreads();

        // S = Q K^T : per-(i,j) f32x2 accumulators over (even d, odd d);
        // LDS.64 on contiguous d-pairs of both Qs and Ks (stride 130 even,
        // banks 2(cb+16j)+d -> conflict-free; Qs is 2-address broadcast).
        u64 acc2[4][4];
#pragma unroll
        for (int i = 0; i < 4; i++)
#pragma unroll
            for (int j = 0; j < 4; j++) acc2[i][j] = 0ULL;

#pragma unroll 2
        for (int d2 = 0; d2 < HDIM / 2; d2++) {
            const int d = d2 * 2;
            u64 k2[4], q2[4];
#pragma unroll
            for (int j = 0; j < 4; j++)
                k2[j] = *(const u64*)&Ks[(cb + 16 * j) * QK_STRIDE + d];
#pragma unroll
            for (int i = 0; i < 4; i++)
                q2[i] = *(const u64*)&Qs[(rb * 4 + i) * QK_STRIDE + d];
#pragma unroll
            for (int i = 0; i < 4; i++)
#pragma unroll
                for (int j = 0; j < 4; j++)
                    FMA2(acc2[i][j], q2[i], k2[j], acc2[i][j]);
        }

        // Horizontal add, causal mask + online softmax (row stats in regs)
        float alpha[4];
#pragma unroll
        for (int i = 0; i < 4; i++) {
            float acc[4];
#pragma unroll
            for (int j = 0; j < 4; j++) {
                float lo, hi;
                UNPACK2(lo, hi, acc2[i][j]);
                acc[j] = lo + hi;
            }
            const int qrow = q0 + rb * 4 + i;
            float mx = -1e30f;
#pragma unroll
            for (int j = 0; j < 4; j++) {
                int kcol = k0 + cb + 16 * j;
                if (kcol > qrow) acc[j] = -1e30f;
                mx = fmaxf(mx, acc[j]);
            }
#pragma unroll
            for (int off = 8; off >= 1; off >>= 1)
                mx = fmaxf(mx, __shfl_xor_sync(0xffffffffu, mx, off));
            float mnew = fmaxf(m[i], mx);
            float p[4], s = 0.f;
#pragma unroll
            for (int j = 0; j < 4; j++) { p[j] = __expf(acc[j] - mnew); s += p[j]; }
#pragma unroll
            for (int off = 8; off >= 1; off >>= 1)
                s += __shfl_xor_sync(0xffffffffu, s, off);
            float al = __expf(m[i] - mnew);
            m[i] = mnew;
            lsum[i] = lsum[i] * al + s;
            alpha[i] = al;
#pragma unroll
            for (int j = 0; j < 4; j++)
                Ps[(rb * 4 + i) * 64 + cb + 16 * j] = p[j];
        }
        __syncthreads();

        // O = O*alpha + P V ; thread cb owns col pairs {cb*2 + j*32}
#pragma unroll
        for (int i = 0; i < 4; i++) {
            u64 al2; PACK_DUP(al2, alpha[i]);
#pragma unroll
            for (int j = 0; j < 4; j++) MUL2(o2[i][j], o2[i][j], al2);
        }

#pragma unroll 2
        for (int k = 0; k < 64; k++) {
            u64 v2[4];
#pragma unroll
            for (int j = 0; j < 4; j++)
                v2[j] = *(const u64*)&Vs[k * 128 + cb * 2 + j * 32];
#pragma unroll
            for (int i = 0; i < 4; i++) {
                u64 p2; PACK_DUP(p2, Ps[(rb * 4 + i) * 64 + k]);
                FMA2(o2[i][0], p2, v2[0], o2[i][0]);
                FMA2(o2[i][1], p2, v2[1], o2[i][1]);
                FMA2(o2[i][2], p2, v2[2], o2[i][2]);
                FMA2(o2[i][3], p2, v2[3], o2[i][3]);
            }
        }
        __syncthreads();
    }

    // Epilogue: normalize + write; thread cb writes float2 at cols cb*2 + j*32
#pragma unroll
    for (int i = 0; i < 4; i++) {
        float inv = 1.f / lsum[i];
        int row = q0 + rb * 4 + i;
        float* op = out + ((size_t)(b * LL + row)) * DD + h * HDIM;
#pragma unroll
        for (int j = 0; j < 4; j++) {
            float x0, x1;
            UNPACK2(x0, x1, o2[i][j]);
            *(float2*)&op[cb * 2 + j * 32] = make_float2(x0 * inv, x1 * inv);
        }
    }
}

// ---------------------------------------------------------------------------
// Launch
// ---------------------------------------------------------------------------
extern "C" void kernel_launch(void* const* d_in, const int* in_sizes, int n_in,
                              void* d_out, int out_size) {
    const float* x    = (const float*)d_in[0];
    const float* cosT = (const float*)d_in[1];
    const float* sinT = (const float*)d_in[2];
    const float* Wqkv = (const float*)d_in[3];
    const float* Wo   = (const float*)d_in[4];
    float* out = (float*)d_out;

    float *qkv, *att;
    cudaGetSymbolAddress((void**)&qkv, g_qkv);
    cudaGetSymbolAddress((void**)&att, g_att);

    // 1) QKV projection with fused RoPE on the q,k regions (cols < 2*DD)
    gemm_nt<<<dim3(6144 / 128, 4096 / 128), 256>>>(x, Wqkv, qkv,
                                                   BB * LL, 3 * DD, DD,
                                                   cosT, sinT, 2 * DD);

    // 2) Causal flash attention
    cudaFuncSetAttribute(attn_kernel, cudaFuncAttributeMaxDynamicSharedMemorySize,
                         SMEM_ATT_BYTES);
    attn_kernel<<<dim3(LL / 64, BB * HH), 256, SMEM_ATT_BYTES>>>(qkv, att);

    // 3) Output projection: [4096,2048] @ [2048,2048]^T -> d_out
    gemm_nt<<<dim3(2048 / 128, 4096 / 128), 256>>>(att, Wo, out,
                                                   BB * LL, DD, DD,
                                                   (const float*)0, (const float*)0, 0);
}